// round 5
// baseline (speedup 1.0000x reference)
#include <cuda_runtime.h>
#include <cuda_bf16.h>

// ---------------------------------------------------------------------------
// 3-layer GCN: h = D^-1/2 (A+I) D^-1/2 (X W) + b, relu after layers 1,2.
//   1. CSR-by-dst per launch: zero + hist + 3-phase multi-block scan + scatter.
//   2. fp32 tiled SGEMM using packed fma.rn.f32x2 (Blackwell FFMA2) with
//      B pre-duplicated in smem so the hot loop is pure LDS.128 + FFMA2.
//   3. Warp-per-node pull aggregation: out[d] = dinv[d]*(g[d]+sum g[src]) + b.
// ---------------------------------------------------------------------------

#define MAXN 50000
#define MAXE 800000
#define SCAN_B 1024
#define SCAN_GRID ((MAXN + SCAN_B - 1) / SCAN_B)   // 49

__device__ float g_h[(size_t)MAXN * 128];   // GEMM output (row-scaled)
__device__ float g_t[(size_t)MAXN * 128];   // aggregation output / next input
__device__ float g_dinv[MAXN];
__device__ int   g_cnt[MAXN];
__device__ int   g_off[MAXN + 1];
__device__ int   g_cur[MAXN];
__device__ int   g_srcs[MAXE];
__device__ int   g_bsum[SCAN_GRID + 1];
__device__ int   g_is64;

__global__ void init_kernel(int n) {
    int i = blockIdx.x * blockDim.x + threadIdx.x;
    if (i < n) { g_cnt[i] = 0; g_cur[i] = 0; }
}

// ---------------------------------------------------------------------------
// Edge dtype detection: int64 values < 50000 have all-zero high words.
// ---------------------------------------------------------------------------
__global__ void detect_kernel(const void* edges, int E) {
    __shared__ int nz;
    if (threadIdx.x == 0) nz = 0;
    __syncthreads();
    const int* w = (const int*)edges;
    int cnt = 0;
    for (int i = threadIdx.x; i < 2048; i += blockDim.x) {
        int idx = 2 * i + 1;
        if (idx < 2 * E && w[idx] != 0) cnt++;
    }
    atomicAdd(&nz, cnt);
    __syncthreads();
    if (threadIdx.x == 0) g_is64 = (nz == 0) ? 1 : 0;
}

__device__ __forceinline__ int edge_val(const void* p, long long idx) {
    if (g_is64) return (int)((const long long*)p)[idx];
    return ((const int*)p)[idx];
}

__global__ void hist_kernel(const void* edges, int E) {
    int e = blockIdx.x * blockDim.x + threadIdx.x;
    if (e < E) {
        int d = edge_val(edges, (long long)E + e);
        atomicAdd(&g_cnt[d], 1);
    }
}

// ---------------------------------------------------------------------------
// Multi-block scan.
// ---------------------------------------------------------------------------
__global__ __launch_bounds__(SCAN_B) void scanA_kernel(int n) {
    __shared__ int wsum[32];
    int gid = blockIdx.x * SCAN_B + threadIdx.x;
    int lane = threadIdx.x & 31;
    int wid = threadIdx.x >> 5;

    int c = (gid < n) ? g_cnt[gid] : 0;
    if (gid < n) g_dinv[gid] = rsqrtf((float)(c + 1));

    int v = c;
#pragma unroll
    for (int o = 1; o < 32; o <<= 1) {
        int u = __shfl_up_sync(0xffffffffu, v, o);
        if (lane >= o) v += u;
    }
    if (lane == 31) wsum[wid] = v;
    __syncthreads();
    if (wid == 0) {
        int w = (lane < SCAN_B / 32) ? wsum[lane] : 0;
#pragma unroll
        for (int o = 1; o < 32; o <<= 1) {
            int u = __shfl_up_sync(0xffffffffu, w, o);
            if (lane >= o) w += u;
        }
        wsum[lane] = w;
    }
    __syncthreads();
    int base = (wid == 0) ? 0 : wsum[wid - 1];
    int excl = base + v - c;
    if (gid < n) g_off[gid] = excl;
    if (threadIdx.x == SCAN_B - 1) g_bsum[blockIdx.x] = base + v;
}

__global__ void scanB_kernel(int n, int E) {
    int lane = threadIdx.x;
    __shared__ int buf[64];
    buf[lane] = (lane < SCAN_GRID) ? g_bsum[lane] : 0;
    __syncthreads();
    if (lane == 0) {
        int run = 0;
        for (int i = 0; i < 64; i++) { int t = buf[i]; buf[i] = run; run += t; }
    }
    __syncthreads();
    if (lane < SCAN_GRID) g_bsum[lane] = buf[lane];
    if (lane == 0) g_off[n] = E;
}

__global__ __launch_bounds__(SCAN_B) void scanC_kernel(int n) {
    int gid = blockIdx.x * SCAN_B + threadIdx.x;
    if (gid < n && blockIdx.x > 0) g_off[gid] += g_bsum[blockIdx.x];
}

__global__ void scatter_kernel(const void* edges, int E) {
    int e = blockIdx.x * blockDim.x + threadIdx.x;
    if (e < E) {
        int d = edge_val(edges, (long long)E + e);
        int s = edge_val(edges, e);
        int pos = g_off[d] + atomicAdd(&g_cur[d], 1);
        g_srcs[pos] = s;
    }
}

// ---------------------------------------------------------------------------
// Packed-f32x2 helpers (Blackwell FFMA2: only reachable via PTX).
// ---------------------------------------------------------------------------
__device__ __forceinline__ void ffma2(unsigned long long& acc,
                                      unsigned long long a,
                                      unsigned long long b) {
    asm("fma.rn.f32x2 %0, %1, %2, %0;" : "+l"(acc) : "l"(a), "l"(b));
}
__device__ __forceinline__ unsigned long long pack2(float v) {
    unsigned long long r;
    asm("mov.b64 %0, {%1, %1};" : "=l"(r) : "f"(v));
    return r;
}

// ---------------------------------------------------------------------------
// Tiled SGEMM: C[M,N] = (A[M,128] @ B[128,N]) * dinv[row]
// acc2[i2][j] packs C rows (r0+2*i2, r0+2*i2+1) at column j.
// Bs2 holds B values pre-duplicated: hot loop = 6 LDS.128 + 32 FFMA2.
// ---------------------------------------------------------------------------
template <int BN, int TN>
__global__ __launch_bounds__(256) void gemm_scale_kernel(
    const float* __restrict__ A, const float* __restrict__ B,
    float* __restrict__ C, int M, int N)
{
    constexpr int BM = 128, BK = 16, TM = 8, K = 128;
    constexpr int THREADS = (BM / TM) * (BN / TN);
    __shared__ float As[BK][BM];                    // 8 KB
    __shared__ unsigned long long Bs2[BK][BN];      // 16 KB (BN=128)

    const int block_row = blockIdx.x * BM;
    const int tid = threadIdx.x;
    const int tcol = tid % (BN / TN);
    const int trow = tid / (BN / TN);

    unsigned long long acc2[TM / 2][TN];
#pragma unroll
    for (int i = 0; i < TM / 2; i++)
#pragma unroll
        for (int j = 0; j < TN; j++) acc2[i][j] = 0ull;

    for (int kt = 0; kt < K; kt += BK) {
        constexpr int A_f4 = BM * BK / 4;
#pragma unroll
        for (int i = tid; i < A_f4; i += THREADS) {
            int r  = i / (BK / 4);
            int c4 = i % (BK / 4);
            float4 v = make_float4(0.f, 0.f, 0.f, 0.f);
            if (block_row + r < M)
                v = *(const float4*)&A[(size_t)(block_row + r) * K + kt + c4 * 4];
            As[c4 * 4 + 0][r] = v.x;
            As[c4 * 4 + 1][r] = v.y;
            As[c4 * 4 + 2][r] = v.z;
            As[c4 * 4 + 3][r] = v.w;
        }
        constexpr int B_f4 = BK * BN / 4;
#pragma unroll
        for (int i = tid; i < B_f4; i += THREADS) {
            int r  = i / (BN / 4);
            int c4 = i % (BN / 4);
            float4 v = *(const float4*)&B[(size_t)(kt + r) * N + c4 * 4];
            Bs2[r][c4 * 4 + 0] = pack2(v.x);
            Bs2[r][c4 * 4 + 1] = pack2(v.y);
            Bs2[r][c4 * 4 + 2] = pack2(v.z);
            Bs2[r][c4 * 4 + 3] = pack2(v.w);
        }
        __syncthreads();
#pragma unroll
        for (int kk = 0; kk < BK; kk++) {
            // A row-pairs: 8 contiguous floats -> 2x LDS.128
            unsigned long long a2[TM / 2];
            {
                ulonglong2 p0 = *(const ulonglong2*)&As[kk][trow * TM + 0];
                ulonglong2 p1 = *(const ulonglong2*)&As[kk][trow * TM + 4];
                a2[0] = p0.x; a2[1] = p0.y; a2[2] = p1.x; a2[3] = p1.y;
            }
            // B duplicated pairs: TN/2 x LDS.128
            unsigned long long b2[TN];
#pragma unroll
            for (int j2 = 0; j2 < TN / 2; j2++) {
                ulonglong2 p = *(const ulonglong2*)&Bs2[kk][tcol * TN + j2 * 2];
                b2[j2 * 2 + 0] = p.x;
                b2[j2 * 2 + 1] = p.y;
            }
#pragma unroll
            for (int i = 0; i < TM / 2; i++)
#pragma unroll
                for (int j = 0; j < TN; j++)
                    ffma2(acc2[i][j], a2[i], b2[j]);
        }
        __syncthreads();
    }

#pragma unroll
    for (int i = 0; i < TM / 2; i++) {
#pragma unroll
        for (int half = 0; half < 2; half++) {
            int r = block_row + trow * TM + i * 2 + half;
            if (r >= M) continue;
            float s = g_dinv[r];
#pragma unroll
            for (int j = 0; j < TN; j += 4) {
                float4 v;
                float2 p0 = *(float2*)&acc2[i][j + 0];
                float2 p1 = *(float2*)&acc2[i][j + 1];
                float2 p2 = *(float2*)&acc2[i][j + 2];
                float2 p3 = *(float2*)&acc2[i][j + 3];
                v.x = (half ? p0.y : p0.x) * s;
                v.y = (half ? p1.y : p1.x) * s;
                v.z = (half ? p2.y : p2.x) * s;
                v.w = (half ? p3.y : p3.x) * s;
                *(float4*)&C[(size_t)r * N + tcol * TN + j] = v;
            }
        }
    }
}

// ---------------------------------------------------------------------------
// Warp-per-node aggregation.
// ---------------------------------------------------------------------------
template <bool RELU>
__global__ void aggregate128_kernel(const float* __restrict__ g,
                                    const float* __restrict__ bias,
                                    float* __restrict__ out, int n)
{
    int warp = (blockIdx.x * blockDim.x + threadIdx.x) >> 5;
    if (warp >= n) return;
    int lane = threadIdx.x & 31;
    const float4* g4 = (const float4*)g;

    float4 acc = g4[(size_t)warp * 32 + lane];   // self-loop term
    int e = g_off[warp];
    int end = g_off[warp + 1];
    while (e < end) {
        int m = min(32, end - e);
        int s = (lane < m) ? g_srcs[e + lane] : 0;
#pragma unroll 4
        for (int j = 0; j < m; j++) {
            int sj = __shfl_sync(0xffffffffu, s, j);
            float4 v = g4[(size_t)sj * 32 + lane];
            acc.x += v.x; acc.y += v.y; acc.z += v.z; acc.w += v.w;
        }
        e += m;
    }
    float sc = g_dinv[warp];
    float4 bv = ((const float4*)bias)[lane];
    float4 o;
    o.x = acc.x * sc + bv.x;
    o.y = acc.y * sc + bv.y;
    o.z = acc.z * sc + bv.z;
    o.w = acc.w * sc + bv.w;
    if (RELU) {
        o.x = fmaxf(o.x, 0.f); o.y = fmaxf(o.y, 0.f);
        o.z = fmaxf(o.z, 0.f); o.w = fmaxf(o.w, 0.f);
    }
    ((float4*)out)[(size_t)warp * 32 + lane] = o;
}

__global__ void aggregate64_kernel(const float* __restrict__ g,
                                   const float* __restrict__ bias,
                                   float* __restrict__ out, int n)
{
    int warp = (blockIdx.x * blockDim.x + threadIdx.x) >> 5;
    if (warp >= n) return;
    int lane = threadIdx.x & 31;
    const float2* g2 = (const float2*)g;

    float2 acc = g2[(size_t)warp * 32 + lane];
    int e = g_off[warp];
    int end = g_off[warp + 1];
    while (e < end) {
        int m = min(32, end - e);
        int s = (lane < m) ? g_srcs[e + lane] : 0;
#pragma unroll 4
        for (int j = 0; j < m; j++) {
            int sj = __shfl_sync(0xffffffffu, s, j);
            float2 v = g2[(size_t)sj * 32 + lane];
            acc.x += v.x; acc.y += v.y;
        }
        e += m;
    }
    float sc = g_dinv[warp];
    float2 bv = ((const float2*)bias)[lane];
    float2 o;
    o.x = acc.x * sc + bv.x;
    o.y = acc.y * sc + bv.y;
    ((float2*)out)[(size_t)warp * 32 + lane] = o;
}

// ---------------------------------------------------------------------------
extern "C" void kernel_launch(void* const* d_in, const int* in_sizes, int n_in,
                              void* d_out, int out_size) {
    const float* x  = (const float*)d_in[0];
    const void*  ei = d_in[1];
    const float* W1 = (const float*)d_in[2];
    const float* b1 = (const float*)d_in[3];
    const float* W2 = (const float*)d_in[4];
    const float* b2 = (const float*)d_in[5];
    const float* W3 = (const float*)d_in[6];
    const float* b3 = (const float*)d_in[7];
    float* out = (float*)d_out;

    const int n = in_sizes[0] / 128;   // 50000
    const int E = in_sizes[1] / 2;     // 800000

    float *h = nullptr, *t = nullptr;
    cudaGetSymbolAddress((void**)&h, g_h);
    cudaGetSymbolAddress((void**)&t, g_t);

    // ---- CSR build ----
    init_kernel<<<(n + 255) / 256, 256>>>(n);
    detect_kernel<<<1, 256>>>(ei, E);
    hist_kernel<<<(E + 255) / 256, 256>>>(ei, E);
    scanA_kernel<<<SCAN_GRID, SCAN_B>>>(n);
    scanB_kernel<<<1, 64>>>(n, E);
    scanC_kernel<<<SCAN_GRID, SCAN_B>>>(n);
    scatter_kernel<<<(E + 255) / 256, 256>>>(ei, E);

    const int gx = (n + 127) / 128;
    const int agg_blocks = (n * 32 + 255) / 256;

    // ---- layer 1 ----
    gemm_scale_kernel<128, 8><<<dim3(gx, 1), 256>>>(x, W1, h, n, 128);
    aggregate128_kernel<true><<<agg_blocks, 256>>>(h, b1, t, n);
    // ---- layer 2 ----
    gemm_scale_kernel<128, 8><<<dim3(gx, 1), 256>>>(t, W2, h, n, 128);
    aggregate128_kernel<true><<<agg_blocks, 256>>>(h, b2, t, n);
    // ---- layer 3 ----
    gemm_scale_kernel<64, 4><<<dim3(gx, 1), 256>>>(t, W3, h, n, 64);
    aggregate64_kernel<<<agg_blocks, 256>>>(h, b3, out, n);
}

// round 6
// speedup vs baseline: 1.8243x; 1.8243x over previous
#include <cuda_runtime.h>
#include <cuda_bf16.h>

// ---------------------------------------------------------------------------
// 3-layer GCN: h = D^-1/2 (A+I) D^-1/2 (X W) + b, relu after layers 1,2.
//   1. CSR-by-dst per launch: zero + hist + 3-phase multi-block scan + scatter.
//   2. fp32 tiled SGEMM, FFMA2 (fma.rn.f32x2) inner loop (R4 structure),
//      persistent-CTA grid-stride over M tiles (no wave-quantization tail).
//   3. Warp-per-node pull aggregation: out[d] = dinv[d]*(g[d]+sum g[src]) + b.
// ---------------------------------------------------------------------------

#define MAXN 50000
#define MAXE 800000
#define SCAN_B 1024
#define SCAN_GRID ((MAXN + SCAN_B - 1) / SCAN_B)   // 49

__device__ float g_h[(size_t)MAXN * 128];   // GEMM output (row-scaled)
__device__ float g_t[(size_t)MAXN * 128];   // aggregation output / next input
__device__ float g_dinv[MAXN];
__device__ int   g_cnt[MAXN];
__device__ int   g_off[MAXN + 1];
__device__ int   g_cur[MAXN];
__device__ int   g_srcs[MAXE];
__device__ int   g_bsum[SCAN_GRID + 1];
__device__ int   g_is64;

__global__ void init_kernel(int n) {
    int i = blockIdx.x * blockDim.x + threadIdx.x;
    if (i < n) { g_cnt[i] = 0; g_cur[i] = 0; }
}

// ---------------------------------------------------------------------------
// Edge dtype detection: int64 values < 50000 have all-zero high words.
// ---------------------------------------------------------------------------
__global__ void detect_kernel(const void* edges, int E) {
    __shared__ int nz;
    if (threadIdx.x == 0) nz = 0;
    __syncthreads();
    const int* w = (const int*)edges;
    int cnt = 0;
    for (int i = threadIdx.x; i < 2048; i += blockDim.x) {
        int idx = 2 * i + 1;
        if (idx < 2 * E && w[idx] != 0) cnt++;
    }
    atomicAdd(&nz, cnt);
    __syncthreads();
    if (threadIdx.x == 0) g_is64 = (nz == 0) ? 1 : 0;
}

__device__ __forceinline__ int edge_val(const void* p, long long idx) {
    if (g_is64) return (int)((const long long*)p)[idx];
    return ((const int*)p)[idx];
}

__global__ void hist_kernel(const void* edges, int E) {
    int e = blockIdx.x * blockDim.x + threadIdx.x;
    if (e < E) {
        int d = edge_val(edges, (long long)E + e);
        atomicAdd(&g_cnt[d], 1);
    }
}

// ---------------------------------------------------------------------------
// Multi-block scan.
// ---------------------------------------------------------------------------
__global__ __launch_bounds__(SCAN_B) void scanA_kernel(int n) {
    __shared__ int wsum[32];
    int gid = blockIdx.x * SCAN_B + threadIdx.x;
    int lane = threadIdx.x & 31;
    int wid = threadIdx.x >> 5;

    int c = (gid < n) ? g_cnt[gid] : 0;
    if (gid < n) g_dinv[gid] = rsqrtf((float)(c + 1));

    int v = c;
#pragma unroll
    for (int o = 1; o < 32; o <<= 1) {
        int u = __shfl_up_sync(0xffffffffu, v, o);
        if (lane >= o) v += u;
    }
    if (lane == 31) wsum[wid] = v;
    __syncthreads();
    if (wid == 0) {
        int w = (lane < SCAN_B / 32) ? wsum[lane] : 0;
#pragma unroll
        for (int o = 1; o < 32; o <<= 1) {
            int u = __shfl_up_sync(0xffffffffu, w, o);
            if (lane >= o) w += u;
        }
        wsum[lane] = w;
    }
    __syncthreads();
    int base = (wid == 0) ? 0 : wsum[wid - 1];
    int excl = base + v - c;
    if (gid < n) g_off[gid] = excl;
    if (threadIdx.x == SCAN_B - 1) g_bsum[blockIdx.x] = base + v;
}

__global__ void scanB_kernel(int n, int E) {
    int lane = threadIdx.x;
    __shared__ int buf[64];
    buf[lane] = (lane < SCAN_GRID) ? g_bsum[lane] : 0;
    __syncthreads();
    if (lane == 0) {
        int run = 0;
        for (int i = 0; i < 64; i++) { int t = buf[i]; buf[i] = run; run += t; }
    }
    __syncthreads();
    if (lane < SCAN_GRID) g_bsum[lane] = buf[lane];
    if (lane == 0) g_off[n] = E;
}

__global__ __launch_bounds__(SCAN_B) void scanC_kernel(int n) {
    int gid = blockIdx.x * SCAN_B + threadIdx.x;
    if (gid < n && blockIdx.x > 0) g_off[gid] += g_bsum[blockIdx.x];
}

__global__ void scatter_kernel(const void* edges, int E) {
    int e = blockIdx.x * blockDim.x + threadIdx.x;
    if (e < E) {
        int d = edge_val(edges, (long long)E + e);
        int s = edge_val(edges, e);
        int pos = g_off[d] + atomicAdd(&g_cur[d], 1);
        g_srcs[pos] = s;
    }
}

// ---------------------------------------------------------------------------
// Packed-f32x2 helpers (Blackwell FFMA2: only reachable via PTX).
// ---------------------------------------------------------------------------
__device__ __forceinline__ void ffma2(unsigned long long& acc,
                                      unsigned long long a,
                                      unsigned long long b) {
    asm("fma.rn.f32x2 %0, %1, %2, %0;" : "+l"(acc) : "l"(a), "l"(b));
}
__device__ __forceinline__ unsigned long long pack2(float v) {
    unsigned long long r;
    asm("mov.b64 %0, {%1, %1};" : "=l"(r) : "f"(v));
    return r;
}

// ---------------------------------------------------------------------------
// Tiled SGEMM: C[M,N] = (A[M,128] @ B[128,N]) * dinv[row]
// R4 inner loop (known good); persistent CTAs loop grid-stride over M tiles.
// ---------------------------------------------------------------------------
template <int BN, int TN>
__global__ __launch_bounds__(256) void gemm_scale_kernel(
    const float* __restrict__ A, const float* __restrict__ B,
    float* __restrict__ C, int M, int N)
{
    constexpr int BM = 128, BK = 16, TM = 8, K = 128;
    constexpr int THREADS = (BM / TM) * (BN / TN);
    __shared__ float As[BK][BM];   // As[k][m] — row pairs contiguous in m
    __shared__ float Bs[BK][BN];

    const int tid = threadIdx.x;
    const int tcol = tid % (BN / TN);
    const int trow = tid / (BN / TN);
    const int n_tiles = (M + BM - 1) / BM;

    for (int tile = blockIdx.x; tile < n_tiles; tile += gridDim.x) {
        const int block_row = tile * BM;

        unsigned long long acc2[TM / 2][TN];
#pragma unroll
        for (int i = 0; i < TM / 2; i++)
#pragma unroll
            for (int j = 0; j < TN; j++) acc2[i][j] = 0ull;

        for (int kt = 0; kt < K; kt += BK) {
            constexpr int A_f4 = BM * BK / 4;
#pragma unroll
            for (int i = tid; i < A_f4; i += THREADS) {
                int r  = i / (BK / 4);
                int c4 = i % (BK / 4);
                float4 v = make_float4(0.f, 0.f, 0.f, 0.f);
                if (block_row + r < M)
                    v = *(const float4*)&A[(size_t)(block_row + r) * K + kt + c4 * 4];
                As[c4 * 4 + 0][r] = v.x;
                As[c4 * 4 + 1][r] = v.y;
                As[c4 * 4 + 2][r] = v.z;
                As[c4 * 4 + 3][r] = v.w;
            }
            constexpr int B_f4 = BK * BN / 4;
#pragma unroll
            for (int i = tid; i < B_f4; i += THREADS) {
                int r  = i / (BN / 4);
                int c4 = i % (BN / 4);
                *(float4*)&Bs[r][c4 * 4] = *(const float4*)&B[(size_t)(kt + r) * N + c4 * 4];
            }
            __syncthreads();
#pragma unroll
            for (int kk = 0; kk < BK; kk++) {
                // A row-pairs: contiguous, 8B-aligned
                unsigned long long a2[TM / 2];
#pragma unroll
                for (int i = 0; i < TM / 2; i++)
                    a2[i] = *(const unsigned long long*)&As[kk][trow * TM + i * 2];
                // B broadcast packs
                unsigned long long b2[TN];
#pragma unroll
                for (int j = 0; j < TN; j++)
                    b2[j] = pack2(Bs[kk][tcol * TN + j]);
#pragma unroll
                for (int i = 0; i < TM / 2; i++)
#pragma unroll
                    for (int j = 0; j < TN; j++)
                        ffma2(acc2[i][j], a2[i], b2[j]);
            }
            __syncthreads();
        }

#pragma unroll
        for (int i = 0; i < TM / 2; i++) {
#pragma unroll
            for (int half = 0; half < 2; half++) {
                int r = block_row + trow * TM + i * 2 + half;
                if (r >= M) continue;
                float s = g_dinv[r];
#pragma unroll
                for (int j = 0; j < TN; j += 4) {
                    float4 v;
                    float2 p0 = *(float2*)&acc2[i][j + 0];
                    float2 p1 = *(float2*)&acc2[i][j + 1];
                    float2 p2 = *(float2*)&acc2[i][j + 2];
                    float2 p3 = *(float2*)&acc2[i][j + 3];
                    v.x = (half ? p0.y : p0.x) * s;
                    v.y = (half ? p1.y : p1.x) * s;
                    v.z = (half ? p2.y : p2.x) * s;
                    v.w = (half ? p3.y : p3.x) * s;
                    *(float4*)&C[(size_t)r * N + tcol * TN + j] = v;
                }
            }
        }
    }
}

// ---------------------------------------------------------------------------
// Warp-per-node aggregation.
// ---------------------------------------------------------------------------
template <bool RELU>
__global__ void aggregate128_kernel(const float* __restrict__ g,
                                    const float* __restrict__ bias,
                                    float* __restrict__ out, int n)
{
    int warp = (blockIdx.x * blockDim.x + threadIdx.x) >> 5;
    if (warp >= n) return;
    int lane = threadIdx.x & 31;
    const float4* g4 = (const float4*)g;

    float4 acc = g4[(size_t)warp * 32 + lane];   // self-loop term
    int e = g_off[warp];
    int end = g_off[warp + 1];
    while (e < end) {
        int m = min(32, end - e);
        int s = (lane < m) ? g_srcs[e + lane] : 0;
#pragma unroll 4
        for (int j = 0; j < m; j++) {
            int sj = __shfl_sync(0xffffffffu, s, j);
            float4 v = g4[(size_t)sj * 32 + lane];
            acc.x += v.x; acc.y += v.y; acc.z += v.z; acc.w += v.w;
        }
        e += m;
    }
    float sc = g_dinv[warp];
    float4 bv = ((const float4*)bias)[lane];
    float4 o;
    o.x = acc.x * sc + bv.x;
    o.y = acc.y * sc + bv.y;
    o.z = acc.z * sc + bv.z;
    o.w = acc.w * sc + bv.w;
    if (RELU) {
        o.x = fmaxf(o.x, 0.f); o.y = fmaxf(o.y, 0.f);
        o.z = fmaxf(o.z, 0.f); o.w = fmaxf(o.w, 0.f);
    }
    ((float4*)out)[(size_t)warp * 32 + lane] = o;
}

__global__ void aggregate64_kernel(const float* __restrict__ g,
                                   const float* __restrict__ bias,
                                   float* __restrict__ out, int n)
{
    int warp = (blockIdx.x * blockDim.x + threadIdx.x) >> 5;
    if (warp >= n) return;
    int lane = threadIdx.x & 31;
    const float2* g2 = (const float2*)g;

    float2 acc = g2[(size_t)warp * 32 + lane];
    int e = g_off[warp];
    int end = g_off[warp + 1];
    while (e < end) {
        int m = min(32, end - e);
        int s = (lane < m) ? g_srcs[e + lane] : 0;
#pragma unroll 4
        for (int j = 0; j < m; j++) {
            int sj = __shfl_sync(0xffffffffu, s, j);
            float2 v = g2[(size_t)sj * 32 + lane];
            acc.x += v.x; acc.y += v.y;
        }
        e += m;
    }
    float sc = g_dinv[warp];
    float2 bv = ((const float2*)bias)[lane];
    float2 o;
    o.x = acc.x * sc + bv.x;
    o.y = acc.y * sc + bv.y;
    ((float2*)out)[(size_t)warp * 32 + lane] = o;
}

// ---------------------------------------------------------------------------
extern "C" void kernel_launch(void* const* d_in, const int* in_sizes, int n_in,
                              void* d_out, int out_size) {
    const float* x  = (const float*)d_in[0];
    const void*  ei = d_in[1];
    const float* W1 = (const float*)d_in[2];
    const float* b1 = (const float*)d_in[3];
    const float* W2 = (const float*)d_in[4];
    const float* b2 = (const float*)d_in[5];
    const float* W3 = (const float*)d_in[6];
    const float* b3 = (const float*)d_in[7];
    float* out = (float*)d_out;

    const int n = in_sizes[0] / 128;   // 50000
    const int E = in_sizes[1] / 2;     // 800000

    float *h = nullptr, *t = nullptr;
    cudaGetSymbolAddress((void**)&h, g_h);
    cudaGetSymbolAddress((void**)&t, g_t);

    // ---- CSR build ----
    init_kernel<<<(n + 255) / 256, 256>>>(n);
    detect_kernel<<<1, 256>>>(ei, E);
    hist_kernel<<<(E + 255) / 256, 256>>>(ei, E);
    scanA_kernel<<<SCAN_GRID, SCAN_B>>>(n);
    scanB_kernel<<<1, 64>>>(n, E);
    scanC_kernel<<<SCAN_GRID, SCAN_B>>>(n);
    scatter_kernel<<<(E + 255) / 256, 256>>>(ei, E);

    // Persistent GEMM grid: 2 CTAs/SM on 148 SMs.
    const int gemm_grid = 296;
    const int agg_blocks = (n * 32 + 255) / 256;

    // ---- layer 1 ----
    gemm_scale_kernel<128, 8><<<gemm_grid, 256>>>(x, W1, h, n, 128);
    aggregate128_kernel<true><<<agg_blocks, 256>>>(h, b1, t, n);
    // ---- layer 2 ----
    gemm_scale_kernel<128, 8><<<gemm_grid, 256>>>(t, W2, h, n, 128);
    aggregate128_kernel<true><<<agg_blocks, 256>>>(h, b2, t, n);
    // ---- layer 3 ----
    gemm_scale_kernel<64, 4><<<gemm_grid, 256>>>(t, W3, h, n, 64);
    aggregate64_kernel<<<agg_blocks, 256>>>(h, b3, out, n);
}

// round 7
// speedup vs baseline: 1.9892x; 1.0904x over previous
#include <cuda_runtime.h>
#include <cuda_fp16.h>

// ---------------------------------------------------------------------------
// 3-layer GCN: h = D^-1/2 (A+I) D^-1/2 (X W) + b, relu after layers 1,2.
//   1. CSR-by-dst per launch: zero + hist + 3-phase multi-block scan + scatter.
//   2. fp32 tiled SGEMM (FFMA2 inner loop, persistent CTAs), epilogue scales
//      by dinv[row] and stores fp16 (halves the L2 gather traffic).
//   3. Warp-per-node pull aggregation (fp16 gathers, fp32 accumulate):
//      out[d] = dinv[d]*(g[d]+sum g[src]) + b.
// ---------------------------------------------------------------------------

#define MAXN 50000
#define MAXE 800000
#define SCAN_B 1024
#define SCAN_GRID ((MAXN + SCAN_B - 1) / SCAN_B)   // 49

__device__ __half g_hh[(size_t)MAXN * 128];  // GEMM output (row-scaled, fp16)
__device__ float  g_t[(size_t)MAXN * 128];   // aggregation output / next input
__device__ float  g_dinv[MAXN];
__device__ int    g_cnt[MAXN];
__device__ int    g_off[MAXN + 1];
__device__ int    g_cur[MAXN];
__device__ int    g_srcs[MAXE];
__device__ int    g_bsum[SCAN_GRID + 1];
__device__ int    g_is64;

__global__ void init_kernel(int n) {
    int i = blockIdx.x * blockDim.x + threadIdx.x;
    if (i < n) { g_cnt[i] = 0; g_cur[i] = 0; }
}

// ---------------------------------------------------------------------------
// Edge dtype detection: int64 values < 50000 have all-zero high words.
// ---------------------------------------------------------------------------
__global__ void detect_kernel(const void* edges, int E) {
    __shared__ int nz;
    if (threadIdx.x == 0) nz = 0;
    __syncthreads();
    const int* w = (const int*)edges;
    int cnt = 0;
    for (int i = threadIdx.x; i < 2048; i += blockDim.x) {
        int idx = 2 * i + 1;
        if (idx < 2 * E && w[idx] != 0) cnt++;
    }
    atomicAdd(&nz, cnt);
    __syncthreads();
    if (threadIdx.x == 0) g_is64 = (nz == 0) ? 1 : 0;
}

__device__ __forceinline__ int edge_val(const void* p, long long idx) {
    if (g_is64) return (int)((const long long*)p)[idx];
    return ((const int*)p)[idx];
}

__global__ void hist_kernel(const void* edges, int E) {
    int e = blockIdx.x * blockDim.x + threadIdx.x;
    if (e < E) {
        int d = edge_val(edges, (long long)E + e);
        atomicAdd(&g_cnt[d], 1);
    }
}

// ---------------------------------------------------------------------------
// Multi-block scan.
// ---------------------------------------------------------------------------
__global__ __launch_bounds__(SCAN_B) void scanA_kernel(int n) {
    __shared__ int wsum[32];
    int gid = blockIdx.x * SCAN_B + threadIdx.x;
    int lane = threadIdx.x & 31;
    int wid = threadIdx.x >> 5;

    int c = (gid < n) ? g_cnt[gid] : 0;
    if (gid < n) g_dinv[gid] = rsqrtf((float)(c + 1));

    int v = c;
#pragma unroll
    for (int o = 1; o < 32; o <<= 1) {
        int u = __shfl_up_sync(0xffffffffu, v, o);
        if (lane >= o) v += u;
    }
    if (lane == 31) wsum[wid] = v;
    __syncthreads();
    if (wid == 0) {
        int w = (lane < SCAN_B / 32) ? wsum[lane] : 0;
#pragma unroll
        for (int o = 1; o < 32; o <<= 1) {
            int u = __shfl_up_sync(0xffffffffu, w, o);
            if (lane >= o) w += u;
        }
        wsum[lane] = w;
    }
    __syncthreads();
    int base = (wid == 0) ? 0 : wsum[wid - 1];
    int excl = base + v - c;
    if (gid < n) g_off[gid] = excl;
    if (threadIdx.x == SCAN_B - 1) g_bsum[blockIdx.x] = base + v;
}

__global__ void scanB_kernel(int n, int E) {
    int lane = threadIdx.x;
    __shared__ int buf[64];
    buf[lane] = (lane < SCAN_GRID) ? g_bsum[lane] : 0;
    __syncthreads();
    if (lane == 0) {
        int run = 0;
        for (int i = 0; i < 64; i++) { int t = buf[i]; buf[i] = run; run += t; }
    }
    __syncthreads();
    if (lane < SCAN_GRID) g_bsum[lane] = buf[lane];
    if (lane == 0) g_off[n] = E;
}

__global__ __launch_bounds__(SCAN_B) void scanC_kernel(int n) {
    int gid = blockIdx.x * SCAN_B + threadIdx.x;
    if (gid < n && blockIdx.x > 0) g_off[gid] += g_bsum[blockIdx.x];
}

__global__ void scatter_kernel(const void* edges, int E) {
    int e = blockIdx.x * blockDim.x + threadIdx.x;
    if (e < E) {
        int d = edge_val(edges, (long long)E + e);
        int s = edge_val(edges, e);
        int pos = g_off[d] + atomicAdd(&g_cur[d], 1);
        g_srcs[pos] = s;
    }
}

// ---------------------------------------------------------------------------
// Packed-f32x2 helpers (Blackwell FFMA2: only reachable via PTX).
// ---------------------------------------------------------------------------
__device__ __forceinline__ void ffma2(unsigned long long& acc,
                                      unsigned long long a,
                                      unsigned long long b) {
    asm("fma.rn.f32x2 %0, %1, %2, %0;" : "+l"(acc) : "l"(a), "l"(b));
}
__device__ __forceinline__ unsigned long long pack2(float v) {
    unsigned long long r;
    asm("mov.b64 %0, {%1, %1};" : "=l"(r) : "f"(v));
    return r;
}

// ---------------------------------------------------------------------------
// Tiled SGEMM: Ch[M,N] = fp16( (A[M,128] @ B[128,N]) * dinv[row] )
// R4 inner loop; persistent CTAs grid-stride over M tiles.
// ---------------------------------------------------------------------------
template <int BN, int TN>
__global__ __launch_bounds__(256) void gemm_scale_kernel(
    const float* __restrict__ A, const float* __restrict__ B,
    __half* __restrict__ Ch, int M, int N)
{
    constexpr int BM = 128, BK = 16, TM = 8, K = 128;
    constexpr int THREADS = (BM / TM) * (BN / TN);
    __shared__ float As[BK][BM];
    __shared__ float Bs[BK][BN];

    const int tid = threadIdx.x;
    const int tcol = tid % (BN / TN);
    const int trow = tid / (BN / TN);
    const int n_tiles = (M + BM - 1) / BM;

    for (int tile = blockIdx.x; tile < n_tiles; tile += gridDim.x) {
        const int block_row = tile * BM;

        unsigned long long acc2[TM / 2][TN];
#pragma unroll
        for (int i = 0; i < TM / 2; i++)
#pragma unroll
            for (int j = 0; j < TN; j++) acc2[i][j] = 0ull;

        for (int kt = 0; kt < K; kt += BK) {
            constexpr int A_f4 = BM * BK / 4;
#pragma unroll
            for (int i = tid; i < A_f4; i += THREADS) {
                int r  = i / (BK / 4);
                int c4 = i % (BK / 4);
                float4 v = make_float4(0.f, 0.f, 0.f, 0.f);
                if (block_row + r < M)
                    v = *(const float4*)&A[(size_t)(block_row + r) * K + kt + c4 * 4];
                As[c4 * 4 + 0][r] = v.x;
                As[c4 * 4 + 1][r] = v.y;
                As[c4 * 4 + 2][r] = v.z;
                As[c4 * 4 + 3][r] = v.w;
            }
            constexpr int B_f4 = BK * BN / 4;
#pragma unroll
            for (int i = tid; i < B_f4; i += THREADS) {
                int r  = i / (BN / 4);
                int c4 = i % (BN / 4);
                *(float4*)&Bs[r][c4 * 4] = *(const float4*)&B[(size_t)(kt + r) * N + c4 * 4];
            }
            __syncthreads();
#pragma unroll
            for (int kk = 0; kk < BK; kk++) {
                unsigned long long a2[TM / 2];
#pragma unroll
                for (int i = 0; i < TM / 2; i++)
                    a2[i] = *(const unsigned long long*)&As[kk][trow * TM + i * 2];
                unsigned long long b2[TN];
#pragma unroll
                for (int j = 0; j < TN; j++)
                    b2[j] = pack2(Bs[kk][tcol * TN + j]);
#pragma unroll
                for (int i = 0; i < TM / 2; i++)
#pragma unroll
                    for (int j = 0; j < TN; j++)
                        ffma2(acc2[i][j], a2[i], b2[j]);
            }
            __syncthreads();
        }

#pragma unroll
        for (int i = 0; i < TM / 2; i++) {
#pragma unroll
            for (int half_ = 0; half_ < 2; half_++) {
                int r = block_row + trow * TM + i * 2 + half_;
                if (r >= M) continue;
                float s = g_dinv[r];
                __align__(16) __half2 hv[TN / 2];
#pragma unroll
                for (int j2 = 0; j2 < TN / 2; j2++) {
                    float2 pa = *(float2*)&acc2[i][j2 * 2 + 0];
                    float2 pb = *(float2*)&acc2[i][j2 * 2 + 1];
                    float v0 = (half_ ? pa.y : pa.x) * s;
                    float v1 = (half_ ? pb.y : pb.x) * s;
                    hv[j2] = __floats2half2_rn(v0, v1);
                }
                __half* dst = &Ch[(size_t)r * N + tcol * TN];
                if (TN == 8)      *(uint4*)dst = *(uint4*)hv;
                else if (TN == 4) *(uint2*)dst = *(uint2*)hv;
            }
        }
    }
}

// ---------------------------------------------------------------------------
// Warp-per-node aggregation: fp16 gathers, fp32 accumulate.
// D=128: lane covers 4 dims = 8 bytes (uint2 of two half2).
// ---------------------------------------------------------------------------
__device__ __forceinline__ float4 gather4h(const __half* g, int row, int lane) {
    uint2 u = *(const uint2*)(g + (size_t)row * 128 + lane * 4);
    __half2 h0 = *(__half2*)&u.x;
    __half2 h1 = *(__half2*)&u.y;
    float2 f0 = __half22float2(h0);
    float2 f1 = __half22float2(h1);
    return make_float4(f0.x, f0.y, f1.x, f1.y);
}

template <bool RELU>
__global__ void aggregate128_kernel(const __half* __restrict__ g,
                                    const float* __restrict__ bias,
                                    float* __restrict__ out, int n)
{
    int warp = (blockIdx.x * blockDim.x + threadIdx.x) >> 5;
    if (warp >= n) return;
    int lane = threadIdx.x & 31;

    float4 acc = gather4h(g, warp, lane);   // self-loop term
    int e = g_off[warp];
    int end = g_off[warp + 1];
    while (e < end) {
        int m = min(32, end - e);
        int s = (lane < m) ? g_srcs[e + lane] : 0;
#pragma unroll 4
        for (int j = 0; j < m; j++) {
            int sj = __shfl_sync(0xffffffffu, s, j);
            float4 v = gather4h(g, sj, lane);
            acc.x += v.x; acc.y += v.y; acc.z += v.z; acc.w += v.w;
        }
        e += m;
    }
    float sc = g_dinv[warp];
    float4 bv = ((const float4*)bias)[lane];
    float4 o;
    o.x = acc.x * sc + bv.x;
    o.y = acc.y * sc + bv.y;
    o.z = acc.z * sc + bv.z;
    o.w = acc.w * sc + bv.w;
    if (RELU) {
        o.x = fmaxf(o.x, 0.f); o.y = fmaxf(o.y, 0.f);
        o.z = fmaxf(o.z, 0.f); o.w = fmaxf(o.w, 0.f);
    }
    ((float4*)out)[(size_t)warp * 32 + lane] = o;
}

// D=64: lane covers 2 dims = 4 bytes (one half2).
__global__ void aggregate64_kernel(const __half* __restrict__ g,
                                   const float* __restrict__ bias,
                                   float* __restrict__ out, int n)
{
    int warp = (blockIdx.x * blockDim.x + threadIdx.x) >> 5;
    if (warp >= n) return;
    int lane = threadIdx.x & 31;

    const __half2* g2 = (const __half2*)g;
    float2 acc = __half22float2(g2[(size_t)warp * 32 + lane]);
    int e = g_off[warp];
    int end = g_off[warp + 1];
    while (e < end) {
        int m = min(32, end - e);
        int s = (lane < m) ? g_srcs[e + lane] : 0;
#pragma unroll 4
        for (int j = 0; j < m; j++) {
            int sj = __shfl_sync(0xffffffffu, s, j);
            float2 v = __half22float2(g2[(size_t)sj * 32 + lane]);
            acc.x += v.x; acc.y += v.y;
        }
        e += m;
    }
    float sc = g_dinv[warp];
    float2 bv = ((const float2*)bias)[lane];
    float2 o;
    o.x = acc.x * sc + bv.x;
    o.y = acc.y * sc + bv.y;
    ((float2*)out)[(size_t)warp * 32 + lane] = o;
}

// ---------------------------------------------------------------------------
extern "C" void kernel_launch(void* const* d_in, const int* in_sizes, int n_in,
                              void* d_out, int out_size) {
    const float* x  = (const float*)d_in[0];
    const void*  ei = d_in[1];
    const float* W1 = (const float*)d_in[2];
    const float* b1 = (const float*)d_in[3];
    const float* W2 = (const float*)d_in[4];
    const float* b2 = (const float*)d_in[5];
    const float* W3 = (const float*)d_in[6];
    const float* b3 = (const float*)d_in[7];
    float* out = (float*)d_out;

    const int n = in_sizes[0] / 128;   // 50000
    const int E = in_sizes[1] / 2;     // 800000

    __half* hh = nullptr;
    float* t = nullptr;
    cudaGetSymbolAddress((void**)&hh, g_hh);
    cudaGetSymbolAddress((void**)&t, g_t);

    // ---- CSR build ----
    init_kernel<<<(n + 255) / 256, 256>>>(n);
    detect_kernel<<<1, 256>>>(ei, E);
    hist_kernel<<<(E + 255) / 256, 256>>>(ei, E);
    scanA_kernel<<<SCAN_GRID, SCAN_B>>>(n);
    scanB_kernel<<<1, 64>>>(n, E);
    scanC_kernel<<<SCAN_GRID, SCAN_B>>>(n);
    scatter_kernel<<<(E + 255) / 256, 256>>>(ei, E);

    // Persistent GEMM grid: 2 CTAs/SM on 148 SMs.
    const int gemm_grid = 296;
    const int agg_blocks = (n * 32 + 255) / 256;

    // ---- layer 1 ----
    gemm_scale_kernel<128, 8><<<gemm_grid, 256>>>(x, W1, hh, n, 128);
    aggregate128_kernel<true><<<agg_blocks, 256>>>(hh, b1, t, n);
    // ---- layer 2 ----
    gemm_scale_kernel<128, 8><<<gemm_grid, 256>>>(t, W2, hh, n, 128);
    aggregate128_kernel<true><<<agg_blocks, 256>>>(hh, b2, t, n);
    // ---- layer 3 ----
    gemm_scale_kernel<64, 4><<<gemm_grid, 256>>>(t, W3, hh, n, 64);
    aggregate64_kernel<<<agg_blocks, 256>>>(hh, b3, out, n);
}

// round 9
// speedup vs baseline: 2.6274x; 1.3209x over previous
#include <cuda_runtime.h>
#include <cuda_fp16.h>
#include <mma.h>
#include <cstdint>

// ---------------------------------------------------------------------------
// 3-layer GCN: h = D^-1/2 (A+I) D^-1/2 (X W) + b, relu after layers 1,2.
//   1. CSR-by-dst per launch: zero + hist + 3-phase multi-block scan + scatter.
//   2. WMMA (HMMA) fp16 GEMM, fp32 accumulate; epilogue scales by dinv[row]
//      and stores fp16 into the gather buffer. (tcgen05 unavailable: harness
//      targets sm_103 without the 'a' feature set.)
//   3. Warp-per-node pull aggregation (fp16 gathers, fp32 accumulate).
// ---------------------------------------------------------------------------

#define MAXN 50000
#define MAXE 800000
#define SCAN_B 1024
#define SCAN_GRID ((MAXN + SCAN_B - 1) / SCAN_B)   // 49

__device__ __half g_hh[(size_t)MAXN * 128];  // GEMM output (row-scaled, fp16)
__device__ float  g_t[(size_t)MAXN * 128];   // aggregation output / next input
__device__ float  g_dinv[MAXN];
__device__ int    g_cnt[MAXN];
__device__ int    g_off[MAXN + 1];
__device__ int    g_cur[MAXN];
__device__ int    g_srcs[MAXE];
__device__ int    g_bsum[SCAN_GRID + 1];
__device__ int    g_is64;

// ---------------------------------------------------------------------------
// CSR build kernels
// ---------------------------------------------------------------------------
__global__ void init_kernel(int n) {
    int i = blockIdx.x * blockDim.x + threadIdx.x;
    if (i < n) { g_cnt[i] = 0; g_cur[i] = 0; }
}

__global__ void detect_kernel(const void* edges, int E) {
    __shared__ int nz;
    if (threadIdx.x == 0) nz = 0;
    __syncthreads();
    const int* w = (const int*)edges;
    int cnt = 0;
    for (int i = threadIdx.x; i < 2048; i += blockDim.x) {
        int idx = 2 * i + 1;
        if (idx < 2 * E && w[idx] != 0) cnt++;
    }
    atomicAdd(&nz, cnt);
    __syncthreads();
    if (threadIdx.x == 0) g_is64 = (nz == 0) ? 1 : 0;
}

__device__ __forceinline__ int edge_val(const void* p, long long idx) {
    if (g_is64) return (int)((const long long*)p)[idx];
    return ((const int*)p)[idx];
}

__global__ void hist_kernel(const void* edges, int E) {
    int e = blockIdx.x * blockDim.x + threadIdx.x;
    if (e < E) {
        int d = edge_val(edges, (long long)E + e);
        atomicAdd(&g_cnt[d], 1);
    }
}

__global__ __launch_bounds__(SCAN_B) void scanA_kernel(int n) {
    __shared__ int wsum[32];
    int gid = blockIdx.x * SCAN_B + threadIdx.x;
    int lane = threadIdx.x & 31;
    int wid = threadIdx.x >> 5;

    int c = (gid < n) ? g_cnt[gid] : 0;
    if (gid < n) g_dinv[gid] = rsqrtf((float)(c + 1));

    int v = c;
#pragma unroll
    for (int o = 1; o < 32; o <<= 1) {
        int u = __shfl_up_sync(0xffffffffu, v, o);
        if (lane >= o) v += u;
    }
    if (lane == 31) wsum[wid] = v;
    __syncthreads();
    if (wid == 0) {
        int w = (lane < SCAN_B / 32) ? wsum[lane] : 0;
#pragma unroll
        for (int o = 1; o < 32; o <<= 1) {
            int u = __shfl_up_sync(0xffffffffu, w, o);
            if (lane >= o) w += u;
        }
        wsum[lane] = w;
    }
    __syncthreads();
    int base = (wid == 0) ? 0 : wsum[wid - 1];
    int excl = base + v - c;
    if (gid < n) g_off[gid] = excl;
    if (threadIdx.x == SCAN_B - 1) g_bsum[blockIdx.x] = base + v;
}

__global__ void scanB_kernel(int n, int E) {
    int lane = threadIdx.x;
    __shared__ int buf[64];
    buf[lane] = (lane < SCAN_GRID) ? g_bsum[lane] : 0;
    __syncthreads();
    if (lane == 0) {
        int run = 0;
        for (int i = 0; i < 64; i++) { int t = buf[i]; buf[i] = run; run += t; }
    }
    __syncthreads();
    if (lane < SCAN_GRID) g_bsum[lane] = buf[lane];
    if (lane == 0) g_off[n] = E;
}

__global__ __launch_bounds__(SCAN_B) void scanC_kernel(int n) {
    int gid = blockIdx.x * SCAN_B + threadIdx.x;
    if (gid < n && blockIdx.x > 0) g_off[gid] += g_bsum[blockIdx.x];
}

__global__ void scatter_kernel(const void* edges, int E) {
    int e = blockIdx.x * blockDim.x + threadIdx.x;
    if (e < E) {
        int d = edge_val(edges, (long long)E + e);
        int s = edge_val(edges, e);
        int pos = g_off[d] + atomicAdd(&g_cur[d], 1);
        g_srcs[pos] = s;
    }
}

// ---------------------------------------------------------------------------
// WMMA fp16 GEMM: Ch[M,N] = fp16( (A[M,128] @ W[128,N]) * dinv[row] )
// 8 warps = 4(M) x 2(N) warp grid; warp tile 32 x (N/2).
// ---------------------------------------------------------------------------
template <int N>
__global__ __launch_bounds__(256) void gemm_wmma_kernel(
    const float* __restrict__ A, const float* __restrict__ W,
    __half* __restrict__ Ch, int M)
{
    using namespace nvcuda;
    constexpr int K = 128, BM = 128;
    constexpr int LDA = K + 16;          // 144 halves (32B-mult rows)
    constexpr int LDW = N + 16;          // 144 or 80 halves
    constexpr int LDS_ = 24;             // staging ldm (fp32, 96B rows)
    constexpr int WMF = 2;               // 32 rows per warp
    constexpr int WNF = N / 32;          // 4 (N=128) or 2 (N=64) frag cols

    extern __shared__ __align__(32) char smem[];
    __half* Wh = (__half*)smem;                              // [K][LDW]
    __half* Ah = (__half*)(smem + (size_t)K * LDW * 2);      // [BM][LDA]
    float* stage = (float*)(smem + (size_t)K * LDW * 2 + (size_t)BM * LDA * 2);

    const int tid = threadIdx.x;
    const int wid = tid >> 5;
    const int lane = tid & 31;
    const int warp_m = wid & 3;
    const int warp_n = wid >> 2;
    float* st = stage + wid * 16 * LDS_;

    // ---- W convert fp32 -> fp16 smem, once per CTA ----
    for (int g = tid; g < K * N / 4; g += 256) {
        int k  = g / (N / 4);
        int c4 = (g % (N / 4)) * 4;
        float4 v = *(const float4*)&W[(size_t)k * N + c4];
        __half2 h01 = __floats2half2_rn(v.x, v.y);
        __half2 h23 = __floats2half2_rn(v.z, v.w);
        uint2 u = make_uint2(*(uint32_t*)&h01, *(uint32_t*)&h23);
        *(uint2*)&Wh[(size_t)k * LDW + c4] = u;
    }

    const int n_tiles = (M + BM - 1) / BM;
    for (int tile = blockIdx.x; tile < n_tiles; tile += gridDim.x) {
        const int brow = tile * BM;

        // ---- A tile convert fp32 -> fp16 smem ----
        for (int g = tid; g < BM * K / 4; g += 256) {
            int r  = g >> 5;
            int c4 = (g & 31) * 4;
            float4 v = make_float4(0.f, 0.f, 0.f, 0.f);
            if (brow + r < M)
                v = *(const float4*)&A[(size_t)(brow + r) * K + c4];
            __half2 h01 = __floats2half2_rn(v.x, v.y);
            __half2 h23 = __floats2half2_rn(v.z, v.w);
            uint2 u = make_uint2(*(uint32_t*)&h01, *(uint32_t*)&h23);
            *(uint2*)&Ah[(size_t)r * LDA + c4] = u;
        }
        __syncthreads();

        // ---- mainloop ----
        wmma::fragment<wmma::accumulator, 16, 16, 16, float> cf[WMF][WNF];
#pragma unroll
        for (int i = 0; i < WMF; i++)
#pragma unroll
            for (int j = 0; j < WNF; j++)
                wmma::fill_fragment(cf[i][j], 0.f);

#pragma unroll
        for (int k = 0; k < K; k += 16) {
            wmma::fragment<wmma::matrix_a, 16, 16, 16, __half, wmma::row_major> af[WMF];
#pragma unroll
            for (int i = 0; i < WMF; i++)
                wmma::load_matrix_sync(af[i],
                    &Ah[(size_t)(warp_m * 32 + i * 16) * LDA + k], LDA);
#pragma unroll
            for (int j = 0; j < WNF; j++) {
                wmma::fragment<wmma::matrix_b, 16, 16, 16, __half, wmma::row_major> bf;
                wmma::load_matrix_sync(bf,
                    &Wh[(size_t)k * LDW + warp_n * WNF * 16 + j * 16], LDW);
#pragma unroll
                for (int i = 0; i < WMF; i++)
                    wmma::mma_sync(cf[i][j], af[i], bf, cf[i][j]);
            }
        }

        // ---- epilogue: stage each 16x16 frag, scale by dinv, fp16 store ----
#pragma unroll
        for (int i = 0; i < WMF; i++) {
#pragma unroll
            for (int j = 0; j < WNF; j++) {
                wmma::store_matrix_sync(st, cf[i][j], LDS_, wmma::mem_row_major);
                __syncwarp();
                int rloc = lane >> 1;
                int cg = (lane & 1) * 8;
                int r = brow + warp_m * 32 + i * 16 + rloc;
                if (r < M) {
                    float s = g_dinv[r];
                    float4 va = *(float4*)&st[rloc * LDS_ + cg + 0];
                    float4 vb = *(float4*)&st[rloc * LDS_ + cg + 4];
                    __align__(16) __half2 hv[4];
                    hv[0] = __floats2half2_rn(va.x * s, va.y * s);
                    hv[1] = __floats2half2_rn(va.z * s, va.w * s);
                    hv[2] = __floats2half2_rn(vb.x * s, vb.y * s);
                    hv[3] = __floats2half2_rn(vb.z * s, vb.w * s);
                    __half* dst = &Ch[(size_t)r * N + warp_n * WNF * 16 + j * 16 + cg];
                    *(uint4*)dst = *(uint4*)hv;
                }
                __syncwarp();
            }
        }
        __syncthreads();   // Ah reused next iteration
    }
}

// ---------------------------------------------------------------------------
// Warp-per-node aggregation: fp16 gathers, fp32 accumulate.
// ---------------------------------------------------------------------------
__device__ __forceinline__ float4 gather4h(const __half* g, int row, int lane) {
    uint2 u = *(const uint2*)(g + (size_t)row * 128 + lane * 4);
    __half2 h0 = *(__half2*)&u.x;
    __half2 h1 = *(__half2*)&u.y;
    float2 f0 = __half22float2(h0);
    float2 f1 = __half22float2(h1);
    return make_float4(f0.x, f0.y, f1.x, f1.y);
}

template <bool RELU>
__global__ void aggregate128_kernel(const __half* __restrict__ g,
                                    const float* __restrict__ bias,
                                    float* __restrict__ out, int n)
{
    int warp = (blockIdx.x * blockDim.x + threadIdx.x) >> 5;
    if (warp >= n) return;
    int lane = threadIdx.x & 31;

    float4 acc = gather4h(g, warp, lane);   // self-loop term
    int e = g_off[warp];
    int end = g_off[warp + 1];
    while (e < end) {
        int m = min(32, end - e);
        int s = (lane < m) ? g_srcs[e + lane] : 0;
#pragma unroll 4
        for (int j = 0; j < m; j++) {
            int sj = __shfl_sync(0xffffffffu, s, j);
            float4 v = gather4h(g, sj, lane);
            acc.x += v.x; acc.y += v.y; acc.z += v.z; acc.w += v.w;
        }
        e += m;
    }
    float sc = g_dinv[warp];
    float4 bv = ((const float4*)bias)[lane];
    float4 o;
    o.x = acc.x * sc + bv.x;
    o.y = acc.y * sc + bv.y;
    o.z = acc.z * sc + bv.z;
    o.w = acc.w * sc + bv.w;
    if (RELU) {
        o.x = fmaxf(o.x, 0.f); o.y = fmaxf(o.y, 0.f);
        o.z = fmaxf(o.z, 0.f); o.w = fmaxf(o.w, 0.f);
    }
    ((float4*)out)[(size_t)warp * 32 + lane] = o;
}

__global__ void aggregate64_kernel(const __half* __restrict__ g,
                                   const float* __restrict__ bias,
                                   float* __restrict__ out, int n)
{
    int warp = (blockIdx.x * blockDim.x + threadIdx.x) >> 5;
    if (warp >= n) return;
    int lane = threadIdx.x & 31;

    const __half2* g2 = (const __half2*)g;
    float2 acc = __half22float2(g2[(size_t)warp * 32 + lane]);
    int e = g_off[warp];
    int end = g_off[warp + 1];
    while (e < end) {
        int m = min(32, end - e);
        int s = (lane < m) ? g_srcs[e + lane] : 0;
#pragma unroll 4
        for (int j = 0; j < m; j++) {
            int sj = __shfl_sync(0xffffffffu, s, j);
            float2 v = __half22float2(g2[(size_t)sj * 32 + lane]);
            acc.x += v.x; acc.y += v.y;
        }
        e += m;
    }
    float sc = g_dinv[warp];
    float2 bv = ((const float2*)bias)[lane];
    float2 o;
    o.x = acc.x * sc + bv.x;
    o.y = acc.y * sc + bv.y;
    ((float2*)out)[(size_t)warp * 32 + lane] = o;
}

// ---------------------------------------------------------------------------
extern "C" void kernel_launch(void* const* d_in, const int* in_sizes, int n_in,
                              void* d_out, int out_size) {
    const float* x  = (const float*)d_in[0];
    const void*  ei = d_in[1];
    const float* W1 = (const float*)d_in[2];
    const float* b1 = (const float*)d_in[3];
    const float* W2 = (const float*)d_in[4];
    const float* b2 = (const float*)d_in[5];
    const float* W3 = (const float*)d_in[6];
    const float* b3 = (const float*)d_in[7];
    float* out = (float*)d_out;

    const int n = in_sizes[0] / 128;   // 50000
    const int E = in_sizes[1] / 2;     // 800000

    __half* hh = nullptr;
    float* t = nullptr;
    cudaGetSymbolAddress((void**)&hh, g_hh);
    cudaGetSymbolAddress((void**)&t, g_t);

    // Dynamic smem: Wh + Ah + staging
    const int smem128 = 128 * 144 * 2 + 128 * 144 * 2 + 8 * 16 * 24 * 4; // 86016
    const int smem64  = 128 * 80 * 2  + 128 * 144 * 2 + 8 * 16 * 24 * 4; // 69632
    cudaFuncSetAttribute(gemm_wmma_kernel<128>,
                         cudaFuncAttributeMaxDynamicSharedMemorySize, smem128);
    cudaFuncSetAttribute(gemm_wmma_kernel<64>,
                         cudaFuncAttributeMaxDynamicSharedMemorySize, smem64);

    // ---- CSR build ----
    init_kernel<<<(n + 255) / 256, 256>>>(n);
    detect_kernel<<<1, 256>>>(ei, E);
    hist_kernel<<<(E + 255) / 256, 256>>>(ei, E);
    scanA_kernel<<<SCAN_GRID, SCAN_B>>>(n);
    scanB_kernel<<<1, 64>>>(n, E);
    scanC_kernel<<<SCAN_GRID, SCAN_B>>>(n);
    scatter_kernel<<<(E + 255) / 256, 256>>>(ei, E);

    const int gemm_grid = 296;   // persistent, 2 CTAs/SM
    const int agg_blocks = (n * 32 + 255) / 256;

    // ---- layer 1 ----
    gemm_wmma_kernel<128><<<gemm_grid, 256, smem128>>>(x, W1, hh, n);
    aggregate128_kernel<true><<<agg_blocks, 256>>>(hh, b1, t, n);
    // ---- layer 2 ----
    gemm_wmma_kernel<128><<<gemm_grid, 256, smem128>>>(t, W2, hh, n);
    aggregate128_kernel<true><<<agg_blocks, 256>>>(hh, b2, t, n);
    // ---- layer 3 ----
    gemm_wmma_kernel<64><<<gemm_grid, 256, smem64>>>(t, W3, hh, n);
    aggregate64_kernel<<<agg_blocks, 256>>>(hh, b3, out, n);
}